// round 17
// baseline (speedup 1.0000x reference)
#include <cuda_runtime.h>

#define NS 64      // states
#define NE 128     // edges = 2*NS
#define PAIRS 2    // row-pairs per warp => 4 rows/warp
#define THREADS 256

// Fixed trellis structure: src(e) = 2*((e>>1)&31) + (e&1).
// For edge block e in [8q, 8q+7]: src(8q+j) = 8*(q&7) + j (consecutive run).
// mask is the 0/1 indicator of this pattern, so w[e] = s2e[src(e),e]*mask[src(e),e].
// Values in s2e / l2e stay fully general (learnable).

__global__ void __launch_bounds__(THREADS)
acs_kernel(const float4* __restrict__ prob4,   // in_prob as [B*16] float4
           const float2* __restrict__ llrs2,   // llrs    as [B]    float2
           const float*  __restrict__ s2e,     // [64, 128]
           const float*  __restrict__ mask,    // [64, 128]
           const float*  __restrict__ l2e,     // [2, 128]
           float4* __restrict__ outm4,         // max as [B*16] float4
           float4* __restrict__ outi4,         // ind as [B*16] float4
           int batch)
{
    __shared__ __align__(16) float sh_w[NE];        // collapsed edge weights
    __shared__ __align__(16) float sh_c[2 * NE];    // l2e rows

    const unsigned tid  = threadIdx.x;
    const unsigned lane = tid & 31u;

    // Stage per-edge constants once per block (coalesced).
    if (tid < NE) {
        const int e = (int)tid;
        const int s = 2 * ((e >> 1) & 31) + (e & 1);   // src(e)
        sh_w[e] = s2e[s * NE + e] * mask[s * NE + e];
    }
    sh_c[tid] = l2e[tid];                               // 256 == 2*NE
    __syncthreads();

    const unsigned wid  = blockIdx.x * (THREADS / 32u) + (tid >> 5);
    const unsigned row0 = wid * (2u * PAIRS);
    if (row0 >= (unsigned)batch) return;

    // lane = 16*h + q: half h owns row (rp + h); lane handles states 4q..4q+3
    const unsigned q  = lane & 15u;
    const unsigned qh = q & 7u;
    const unsigned h  = lane >> 4;

    // Edge-block constants for edges 8q..8q+7 (conflict-free LDS.128 pairs).
    const float4 w0 = ((const float4*)sh_w)[2u * q];
    const float4 w1 = ((const float4*)sh_w)[2u * q + 1u];
    const float4 a0 = ((const float4*)sh_c)[2u * q];          // l2e row 0
    const float4 a1 = ((const float4*)sh_c)[2u * q + 1u];
    const float4 d0 = ((const float4*)(sh_c + NE))[2u * q];   // l2e row 1
    const float4 d1 = ((const float4*)(sh_c + NE))[2u * q + 1u];

    // Front-batched streaming loads: per row, lanes fetch sources 8qh..8qh+7
    // (2-way address dup q vs q+8 within a half — identical to the proven engine).
    float4 pa[PAIRS], pb[PAIRS];
    float2 L[PAIRS];
    unsigned row[PAIRS];
    #pragma unroll
    for (unsigned t = 0; t < PAIRS; t++) {
        row[t] = row0 + 2u * t + h;
        if (row[t] < (unsigned)batch) {
            const unsigned base = row[t] * 16u;
            pa[t] = __ldcs(&prob4[base + 2u * qh]);        // sources 8qh..8qh+3
            pb[t] = __ldcs(&prob4[base + 2u * qh + 1u]);   // sources 8qh+4..8qh+7
            L[t]  = __ldcs(&llrs2[row[t]]);                // half-warp broadcast
        }
    }

    #pragma unroll
    for (unsigned t = 0; t < PAIRS; t++) {
        if (row[t] >= (unsigned)batch) continue;

        const float lx = L[t].x, ly = L[t].y;

        // x[j] = prob[row, 8qh+j]*w[8q+j] + lx*l2e0[8q+j] + ly*l2e1[8q+j]
        const float x0 = fmaf(pa[t].x, w0.x, fmaf(lx, a0.x, ly * d0.x));
        const float x1 = fmaf(pa[t].y, w0.y, fmaf(lx, a0.y, ly * d0.y));
        const float x2 = fmaf(pa[t].z, w0.z, fmaf(lx, a0.z, ly * d0.z));
        const float x3 = fmaf(pa[t].w, w0.w, fmaf(lx, a0.w, ly * d0.w));
        const float x4 = fmaf(pb[t].x, w1.x, fmaf(lx, a1.x, ly * d1.x));
        const float x5 = fmaf(pb[t].y, w1.y, fmaf(lx, a1.y, ly * d1.y));
        const float x6 = fmaf(pb[t].z, w1.z, fmaf(lx, a1.z, ly * d1.z));
        const float x7 = fmaf(pb[t].w, w1.w, fmaf(lx, a1.w, ly * d1.w));

        // compare-select for states 4q..4q+3 (argmax tie -> 0)
        float4 mx, id;
        mx.x = fmaxf(x0, x1); id.x = (x1 > x0) ? 1.0f : 0.0f;
        mx.y = fmaxf(x2, x3); id.y = (x3 > x2) ? 1.0f : 0.0f;
        mx.z = fmaxf(x4, x5); id.z = (x5 > x4) ? 1.0f : 0.0f;
        mx.w = fmaxf(x6, x7); id.w = (x7 > x6) ? 1.0f : 0.0f;

        // Half-warp writes a full contiguous 256B row segment per stream.
        const unsigned o = row[t] * 16u + q;
        __stcs(&outm4[o], mx);
        __stcs(&outi4[o], id);
    }
}

extern "C" void kernel_launch(void* const* d_in, const int* in_sizes, int n_in,
                              void* d_out, int out_size) {
    const float* in_prob = (const float*)d_in[0];   // [B, 64]
    const float* llrs    = (const float*)d_in[1];   // [B, 2]
    const float* s2e     = (const float*)d_in[2];   // [64, 128]
    const float* mask    = (const float*)d_in[3];   // [64, 128]
    const float* l2e     = (const float*)d_in[4];   // [2, 128]

    const int batch = in_sizes[0] / NS;

    float* out_max = (float*)d_out;                          // [B, 64]
    float* out_ind = (float*)d_out + (long long)batch * NS;  // [B, 64]

    const int rows_per_warp = 2 * PAIRS;
    const long long warps = ((long long)batch + rows_per_warp - 1) / rows_per_warp;
    const int blocks = (int)((warps + (THREADS / 32) - 1) / (THREADS / 32));

    acs_kernel<<<blocks, THREADS>>>((const float4*)in_prob,
                                    (const float2*)llrs,
                                    s2e, mask, l2e,
                                    (float4*)out_max,
                                    (float4*)out_ind,
                                    batch);
}